// round 7
// baseline (speedup 1.0000x reference)
#include <cuda_runtime.h>
#include <cfloat>
#include <math.h>

// VectorQuantizer R7: int8 dp4a filter GEMM (exact integer dots, provable
// error bound) + lossless candidate pruning + exact fp32 rescore that is
// bit-identical to the validated R2 FFMA2 kernel.
// x:[65536,256] f32, cb:[1024,256] f32.
// out: [ y (N*D) | idx as float (N) | loss | perplexity | usage | H ]

#define D 256
#define D4 64
#define KCB 1024
#define N_FIXED 65536
#define CAND_CAP 32

// filter smem layout (bytes)
#define XQ_OFF   0          // 128 rows * 68 u32 = 34816
#define CB_OFF   34816      // 2 * (64*132 u32) = 67584
#define CBBUF_B  33792
#define E2_OFF   102400     // 1024 f32
#define FA_OFF   106496     // 128 f32
#define TAU_OFF  107008     // 128 f32
#define X2_OFF   107520     // 128 f32
#define RMN_OFF  108032     // 128 i32
#define CNT_OFF  108544     // 128 i32
#define CK_OFF   109056     // 128*32 u16 = 8192
#define SMEM_TOTAL 117248

__device__ int          g_idx[N_FIXED];
__device__ float        g_e2[KCB];
__device__ float        g_x2[N_FIXED];
__device__ float        g_sx[N_FIXED];
__device__ float        g_x1[N_FIXED];
__device__ unsigned int g_counts[KCB];
__device__ double       g_partial[N_FIXED / 32];
__device__ unsigned int g_xq[N_FIXED * D4];   // int8 x, 4/word
__device__ unsigned int g_cbq[KCB * D4];      // int8 codebook, 4/word
__device__ unsigned int g_cmax_bits;
__device__ unsigned int g_c1max_bits;

// ---------------- helpers ----------------
__device__ __forceinline__ unsigned int packs8(float a, float b, float c, float d) {
    int ia = (int)a, ib = (int)b, ic = (int)c, id = (int)d;
    return (unsigned)(ia & 0xff) | ((unsigned)(ib & 0xff) << 8) |
           ((unsigned)(ic & 0xff) << 16) | ((unsigned)(id & 0xff) << 24);
}
__device__ __forceinline__ float q127(float v, float inv) {
    return fminf(127.0f, fmaxf(-127.0f, rintf(v * inv)));
}
// exact sequential fp32 dot, d ascending (matches R2 per-code chain)
__device__ __forceinline__ float seqdot256(const float* __restrict__ xr,
                                           const float* __restrict__ cr) {
    float s = 0.0f;
#pragma unroll 16
    for (int d = 0; d < 256; ++d)
        s = fmaf(__ldg(xr + d), __ldg(cr + d), s);
    return s;
}

// ---------------- setup ----------------
__global__ void vq_init_kernel() {
    int t = threadIdx.x;
    if (t < KCB) g_counts[t] = 0u;
    if (t == 0) { g_cmax_bits = 0u; g_c1max_bits = 0u; }
}

// e2[k], per-code |c|max and ||c||1 -> global maxima
__global__ void vq_e2_kernel(const float* __restrict__ cb) {
    int row  = blockIdx.x * 8 + (threadIdx.x >> 5);
    int lane = threadIdx.x & 31;
    float s = 0.0f, mx = 0.0f, s1 = 0.0f;
#pragma unroll
    for (int j = 0; j < 8; ++j) {
        float v = cb[row * D + lane + j * 32];
        s = fmaf(v, v, s);
        float a = fabsf(v);
        mx = fmaxf(mx, a);
        s1 += a;
    }
#pragma unroll
    for (int m = 16; m >= 1; m >>= 1) {
        s  += __shfl_xor_sync(0xffffffffu, s, m);
        s1 += __shfl_xor_sync(0xffffffffu, s1, m);
        mx  = fmaxf(mx, __shfl_xor_sync(0xffffffffu, mx, m));
    }
    if (lane == 0) {
        g_e2[row] = s;
        atomicMax(&g_cmax_bits, __float_as_uint(mx));
        atomicMax(&g_c1max_bits, __float_as_uint(s1));
    }
}

// quantize codebook with global scale
__global__ void vq_cq_kernel(const float* __restrict__ cb) {
    int idx = blockIdx.x * 256 + threadIdx.x;     // 0..65535
    float cmax = __uint_as_float(g_cmax_bits);
    float inv  = 127.0f / fmaxf(cmax, 1e-30f);
    int base = idx * 4;
    float a = cb[base], b = cb[base + 1], c = cb[base + 2], d = cb[base + 3];
    g_cbq[idx] = packs8(q127(a, inv), q127(b, inv), q127(c, inv), q127(d, inv));
}

// per-row: exact R2 x2, max|x|, ||x||1, int8 quantized x
__global__ void __launch_bounds__(256)
vq_xq_kernel(const float* __restrict__ x) {
    const int tid = threadIdx.x;
    const int tx  = tid & 15;
    const int ty  = tid >> 4;
    const int n0  = blockIdx.x * 128;
    const float4* __restrict__ x4 = (const float4*)x;
#pragma unroll 1
    for (int i = 0; i < 8; ++i) {
        int n = n0 + ty * 8 + i;
        float4 v[4];
        float s = 0.0f;
#pragma unroll
        for (int q = 0; q < 4; ++q) {           // EXACT R2 x2 chain
            v[q] = x4[(size_t)n * D4 + tx * 4 + q];
            s = fmaf(v[q].x, v[q].x, s);
            s = fmaf(v[q].y, v[q].y, s);
            s = fmaf(v[q].z, v[q].z, s);
            s = fmaf(v[q].w, v[q].w, s);
        }
        float mx = 0.0f, s1 = 0.0f;
#pragma unroll
        for (int q = 0; q < 4; ++q) {
            mx = fmaxf(mx, fmaxf(fmaxf(fabsf(v[q].x), fabsf(v[q].y)),
                                 fmaxf(fabsf(v[q].z), fabsf(v[q].w))));
            s1 += fabsf(v[q].x) + fabsf(v[q].y) + fabsf(v[q].z) + fabsf(v[q].w);
        }
#pragma unroll
        for (int m = 8; m >= 1; m >>= 1) {
            s  += __shfl_xor_sync(0xffffffffu, s, m, 16);
            s1 += __shfl_xor_sync(0xffffffffu, s1, m, 16);
            mx  = fmaxf(mx, __shfl_xor_sync(0xffffffffu, mx, m, 16));
        }
        float inv = 127.0f / fmaxf(mx, 1e-30f);
        uint4 w;
        w.x = packs8(q127(v[0].x, inv), q127(v[0].y, inv), q127(v[0].z, inv), q127(v[0].w, inv));
        w.y = packs8(q127(v[1].x, inv), q127(v[1].y, inv), q127(v[1].z, inv), q127(v[1].w, inv));
        w.z = packs8(q127(v[2].x, inv), q127(v[2].y, inv), q127(v[2].z, inv), q127(v[2].w, inv));
        w.w = packs8(q127(v[3].x, inv), q127(v[3].y, inv), q127(v[3].z, inv), q127(v[3].w, inv));
        *(uint4*)(&g_xq[(size_t)n * D4 + tx * 4]) = w;
        if (tx == 0) {
            g_x2[n] = s;
            g_sx[n] = mx * (1.0f / 127.0f);
            g_x1[n] = s1;
        }
    }
}

// ---------------- dp4a filter + exact select ----------------
__global__ void __launch_bounds__(256, 1)
vq_filter_kernel(const float* __restrict__ x, const float* __restrict__ cb) {
    extern __shared__ char smem[];
    unsigned int*   xqs = (unsigned int*)(smem + XQ_OFF);
    float*          e2s = (float*)(smem + E2_OFF);
    float*          fAs = (float*)(smem + FA_OFF);
    float*          tas = (float*)(smem + TAU_OFF);
    float*          x2s = (float*)(smem + X2_OFF);
    int*            rmn = (int*)(smem + RMN_OFF);
    int*            cnt = (int*)(smem + CNT_OFF);
    unsigned short* ck  = (unsigned short*)(smem + CK_OFF);

    const int tid = threadIdx.x;
    const int tx  = tid & 15;
    const int ty  = tid >> 4;
    const int n0  = blockIdx.x * 128;

    const float cmax  = __uint_as_float(g_cmax_bits);
    const float c1max = __uint_as_float(g_c1max_bits);
    const float sc    = cmax * (1.0f / 127.0f);

    for (int i = tid; i < KCB; i += 256) e2s[i] = g_e2[i];
    if (tid < 128) {
        int n = n0 + tid;
        float sx = g_sx[n];
        fAs[tid] = sx * sc;
        tas[tid] = 1.01f * (sc * g_x1[n] + sx * c1max)
                 + 400.0f * sx * sc + 5e-4f;
        x2s[tid] = g_x2[n];
        rmn[tid] = 0x7F7FFFFF;
        cnt[tid] = 0;
    }

    const uint4* __restrict__ gxq4 = (const uint4*)g_xq;
    const uint4* __restrict__ gcq4 = (const uint4*)g_cbq;

    // load x int8 tile: 128 rows x 16 uint4, smem stride 17 uint4 (68 words)
    {
        uint4* xq4 = (uint4*)xqs;
#pragma unroll
        for (int u = 0; u < 8; ++u) {
            int f = tid + u * 256;         // 0..2047
            int r = f >> 4, q = f & 15;
            xq4[r * 17 + q] = gxq4[(size_t)(n0 + r) * 16 + q];
        }
    }
    // load code chunk 0, transposed [dd][code] with bank swizzle
    {
        unsigned int* dst = (unsigned int*)(smem + CB_OFF);
#pragma unroll
        for (int u = 0; u < 8; ++u) {
            int f = tid + u * 256;
            int k = f >> 4, q = f & 15;
            uint4 v = gcq4[(size_t)k * 16 + q];
            int sw = k ^ (((k >> 5) & 3) << 3);
            dst[(4 * q + 0) * 132 + sw] = v.x;
            dst[(4 * q + 1) * 132 + sw] = v.y;
            dst[(4 * q + 2) * 132 + sw] = v.z;
            dst[(4 * q + 3) * 132 + sw] = v.w;
        }
    }
    __syncthreads();

    const uint4* xq4r = (const uint4*)xqs;
    const int cwq = ((8 * tx) ^ ((tx >> 2) << 3)) >> 2;   // uint4 offset in code row

#pragma unroll 1
    for (int ch = 0; ch < 8; ++ch) {
        // prefetch next chunk into regs
        uint4 pv[8];
        if (ch < 7) {
#pragma unroll
            for (int u = 0; u < 8; ++u) {
                int f = tid + u * 256;
                int k = f >> 4, q = f & 15;
                pv[u] = gcq4[(size_t)((ch + 1) * 128 + k) * 16 + q];
            }
        }

        int acc[8][8];
#pragma unroll
        for (int i = 0; i < 8; ++i)
#pragma unroll
            for (int j = 0; j < 8; ++j) acc[i][j] = 0;

        const uint4* cb4 = (const uint4*)(smem + CB_OFF + (ch & 1) * CBBUF_B);
#pragma unroll 4
        for (int dd4 = 0; dd4 < 16; ++dd4) {
            uint4 xw[8];
#pragma unroll
            for (int i = 0; i < 8; ++i)
                xw[i] = xq4r[(ty * 8 + i) * 17 + dd4];
#pragma unroll
            for (int sub = 0; sub < 4; ++sub) {
                const uint4* cp = cb4 + (dd4 * 4 + sub) * 33 + cwq;
                uint4 c0 = cp[0];
                uint4 c1 = cp[1];
#pragma unroll
                for (int i = 0; i < 8; ++i) {
                    int xs = (sub == 0) ? (int)xw[i].x : (sub == 1) ? (int)xw[i].y
                           : (sub == 2) ? (int)xw[i].z : (int)xw[i].w;
                    acc[i][0] = __dp4a(xs, (int)c0.x, acc[i][0]);
                    acc[i][1] = __dp4a(xs, (int)c0.y, acc[i][1]);
                    acc[i][2] = __dp4a(xs, (int)c0.z, acc[i][2]);
                    acc[i][3] = __dp4a(xs, (int)c0.w, acc[i][3]);
                    acc[i][4] = __dp4a(xs, (int)c1.x, acc[i][4]);
                    acc[i][5] = __dp4a(xs, (int)c1.y, acc[i][5]);
                    acc[i][6] = __dp4a(xs, (int)c1.z, acc[i][6]);
                    acc[i][7] = __dp4a(xs, (int)c1.w, acc[i][7]);
                }
            }
        }

        // store prefetched chunk to other buffer
        if (ch < 7) {
            unsigned int* dst = (unsigned int*)(smem + CB_OFF + ((ch + 1) & 1) * CBBUF_B);
#pragma unroll
            for (int u = 0; u < 8; ++u) {
                int f = tid + u * 256;
                int k = f >> 4, q = f & 15;
                int sw = k ^ (((k >> 5) & 3) << 3);
                dst[(4 * q + 0) * 132 + sw] = pv[u].x;
                dst[(4 * q + 1) * 132 + sw] = pv[u].y;
                dst[(4 * q + 2) * 132 + sw] = pv[u].z;
                dst[(4 * q + 3) * 132 + sw] = pv[u].w;
            }
        }

        // epilogue 1: approx dists + running row min
        const int kb = ch * 128 + tx * 8;
#pragma unroll
        for (int i = 0; i < 8; ++i) {
            int r = ty * 8 + i;
            float fA = -2.0f * fAs[r];
            float xe = x2s[r];
            float mn = FLT_MAX;
#pragma unroll
            for (int j = 0; j < 8; ++j) {
                float dd = fmaf(fA, (float)acc[i][j], xe + e2s[kb + j]);
                mn = fminf(mn, dd);
            }
#pragma unroll
            for (int m = 8; m >= 1; m >>= 1)
                mn = fminf(mn, __shfl_xor_sync(0xffffffffu, mn, m, 16));
            if (tx == 0) atomicMin(&rmn[r], __float_as_int(mn));
        }
        __syncthreads();

        // epilogue 2: collect candidates (min only shrinks -> never misses)
#pragma unroll
        for (int i = 0; i < 8; ++i) {
            int r = ty * 8 + i;
            float thr = __int_as_float(rmn[r]) + tas[r];
            float fA = -2.0f * fAs[r];
            float xe = x2s[r];
#pragma unroll
            for (int j = 0; j < 8; ++j) {
                float dd = fmaf(fA, (float)acc[i][j], xe + e2s[kb + j]);
                if (dd <= thr) {
                    int p = atomicAdd(&cnt[r], 1);
                    if (p < CAND_CAP)
                        ck[r * CAND_CAP + p] = (unsigned short)(kb + j);
                }
            }
        }
        __syncthreads();
    }

    // exact selection: quad of lanes per row (validated in R5)
    const int w    = tid >> 5;
    const int lane = tid & 31;
#pragma unroll 1
    for (int batch = 0; batch < 2; ++batch) {
        int r  = w * 16 + batch * 8 + (lane >> 2);
        int li = lane & 3;
        int n  = n0 + r;
        int c  = cnt[r];
        const float* xr = x + (size_t)n * D;
        float x2v = x2s[r];

        float bd = FLT_MAX;
        int   bk = 0x7fffffff;
        if (c <= CAND_CAP) {
            for (int j = li; j < c; j += 4) {
                int k = ck[r * CAND_CAP + j];
                float s  = seqdot256(xr, cb + (size_t)k * D);
                float dd = __fadd_rn(__fadd_rn(x2v, e2s[k]), -__fmul_rn(2.0f, s));
                if (dd < bd || (dd == bd && k < bk)) { bd = dd; bk = k; }
            }
        } else {   // overflow fallback: exact full scan
            for (int k = li; k < KCB; k += 4) {
                float s  = seqdot256(xr, cb + (size_t)k * D);
                float dd = __fadd_rn(__fadd_rn(x2v, e2s[k]), -__fmul_rn(2.0f, s));
                if (dd < bd || (dd == bd && k < bk)) { bd = dd; bk = k; }
            }
        }
#pragma unroll
        for (int m = 1; m <= 2; m <<= 1) {
            float od = __shfl_xor_sync(0xffffffffu, bd, m);
            int   ok = __shfl_xor_sync(0xffffffffu, bk, m);
            if (od < bd || (od == bd && ok < bk)) { bd = od; bk = ok; }
        }
        if (li == 0) g_idx[n] = bk;
    }
}

// ---------------- gather (validated) ----------------
__global__ void __launch_bounds__(256)
vq_gather_kernel(const float* __restrict__ x, const float* __restrict__ cb,
                 float* __restrict__ y_out, float* __restrict__ idxf_out) {
    __shared__ double wsum[8];
    const int tid  = threadIdx.x;
    const int wid  = tid >> 5;
    const int lane = tid & 31;
    const int nb   = blockIdx.x * 32 + wid * 4;

    int k4[4];
#pragma unroll
    for (int rr = 0; rr < 4; ++rr) k4[rr] = g_idx[nb + rr];

    const float4* x4  = (const float4*)x;
    const float4* cb4 = (const float4*)cb;
    float4* y4 = (float4*)y_out;

    double acc = 0.0;
#pragma unroll
    for (int rr = 0; rr < 4; ++rr) {
        int n = nb + rr;
        int k = k4[rr];
#pragma unroll
        for (int u = 0; u < 2; ++u) {
            int d4 = lane + u * 32;
            float4 xv = x4[(size_t)n * D4 + d4];
            float4 qv = cb4[(size_t)k * D4 + d4];
            float tx_ = __fadd_rn(qv.x, -xv.x);
            float ty_ = __fadd_rn(qv.y, -xv.y);
            float tz_ = __fadd_rn(qv.z, -xv.z);
            float tw_ = __fadd_rn(qv.w, -xv.w);
            float4 yv;
            yv.x = __fadd_rn(xv.x, tx_);
            yv.y = __fadd_rn(xv.y, ty_);
            yv.z = __fadd_rn(xv.z, tz_);
            yv.w = __fadd_rn(xv.w, tw_);
            y4[(size_t)n * D4 + d4] = yv;
            acc += (double)tx_ * tx_ + (double)ty_ * ty_ +
                   (double)tz_ * tz_ + (double)tw_ * tw_;
        }
        if (lane == 0) {
            atomicAdd(&g_counts[k], 1u);
            if (idxf_out) idxf_out[n] = (float)k;
        }
    }

#pragma unroll
    for (int m = 16; m >= 1; m >>= 1)
        acc += __shfl_xor_sync(0xffffffffu, acc, m);
    if (lane == 0) wsum[wid] = acc;
    __syncthreads();
    if (tid == 0) {
        double s = 0.0;
#pragma unroll
        for (int i = 0; i < 8; ++i) s += wsum[i];
        g_partial[blockIdx.x] = s;
    }
}

__global__ void __launch_bounds__(1024)
vq_finalize_kernel(float* __restrict__ scal_out, int nblocks_gather) {
    __shared__ double redH[1024];
    __shared__ double redU[1024];
    __shared__ double redS[1024];
    int t = threadIdx.x;

    double s = 0.0;
    for (int i = t; i < nblocks_gather; i += 1024) s += g_partial[i];

    float p    = (float)g_counts[t] * (1.0f / 65536.0f);
    float term = p * log2f(p + 1e-10f);

    redH[t] = -(double)term;
    redU[t] = (p > 0.0f) ? 1.0 : 0.0;
    redS[t] = s;
    __syncthreads();
#pragma unroll
    for (int m = 512; m >= 1; m >>= 1) {
        if (t < m) {
            redH[t] += redH[t + m];
            redU[t] += redU[t + m];
            redS[t] += redS[t + m];
        }
        __syncthreads();
    }
    if (t == 0) {
        double mse  = redS[0] / (double)((size_t)N_FIXED * D);
        float  c     = (float)mse;
        float  loss  = __fadd_rn(__fmul_rn(0.25f, c), c);
        float  H     = (float)redH[0];
        float  perp  = expf(__fmul_rn(H, 0.69314718f));
        float  usage = (float)(redU[0] / 1024.0);
        scal_out[0] = loss;
        scal_out[1] = perp;
        scal_out[2] = usage;
        scal_out[3] = H;
    }
}

extern "C" void kernel_launch(void* const* d_in, const int* in_sizes, int n_in,
                              void* d_out, int out_size) {
    (void)n_in;
    const float* x  = (const float*)d_in[0];
    const float* cb = (const float*)d_in[1];
    float* out = (float*)d_out;

    const int    n  = in_sizes[0] / D;      // 65536
    const size_t ND = (size_t)n * D;

    const long long os = (long long)out_size;
    const int with_idx  = os >= (long long)(ND + (size_t)n);
    const int with_scal = os >= (long long)(ND + (size_t)n + 4);

    cudaFuncSetAttribute(vq_filter_kernel,
                         cudaFuncAttributeMaxDynamicSharedMemorySize, SMEM_TOTAL);

    vq_init_kernel<<<1, 1024>>>();
    vq_e2_kernel<<<KCB / 8, 256>>>(cb);
    vq_cq_kernel<<<(KCB * D4) / 256, 256>>>(cb);
    vq_xq_kernel<<<n / 128, 256>>>(x);
    vq_filter_kernel<<<n / 128, 256, SMEM_TOTAL>>>(x, cb);
    vq_gather_kernel<<<n / 32, 256>>>(x, cb, out,
                                      with_idx ? (out + ND) : (float*)0);
    if (with_scal)
        vq_finalize_kernel<<<1, 1024>>>(out + ND + n, n / 32);
}

// round 8
// speedup vs baseline: 2.1436x; 2.1436x over previous
#include <cuda_runtime.h>
#include <cfloat>
#include <math.h>

// VectorQuantizer R8: R2 FFMA2 argmin mainloop (at ~96% of its rt3
// register-bank floor) with gather/histogram/SSE/idx fused into the same
// kernel. Numerics byte-identical to R2 for idx and y.
// out: [ y (N*D) | idx as float (N) | loss | perplexity | usage | H ]

#define N_FIXED 65536
#define D 256
#define D4 64
#define KCB 1024
#define BN 128
#define XS_STRIDE4 65   // x smem row stride in float4
#define CS_STRIDE 132   // code smem row stride in floats
#define SMEM_FLOATS (128 * 260 + 2 * 32 * CS_STRIDE + 1024 + 128 + 16 + 16)
// layout: xs | cs(2 bufs) | e2s | idx_s(128 int) | wsum(8 dbl as 16 f) | pad

__device__ float        g_e2[KCB];
__device__ unsigned int g_counts[KCB];
__device__ double       g_partial[512];

#define FMA2(d, a, b) \
    asm("fma.rn.f32x2 %0, %1, %2, %0;" : "+l"(d) : "l"(a), "l"(b))

__device__ __forceinline__ unsigned long long bcast2(float v) {
    unsigned long long r;
    asm("mov.b64 %0, {%1, %1};" : "=l"(r) : "f"(v));
    return r;
}

__global__ void vq_init_kernel() {
    int t = threadIdx.x;
    if (t < KCB) g_counts[t] = 0u;
}

__global__ void vq_e2_kernel(const float* __restrict__ cb) {
    int row  = blockIdx.x * 8 + (threadIdx.x >> 5);
    int lane = threadIdx.x & 31;
    float s = 0.0f;
#pragma unroll
    for (int j = 0; j < 8; ++j) {
        float v = cb[row * D + lane + j * 32];
        s = fmaf(v, v, s);
    }
#pragma unroll
    for (int m = 16; m >= 1; m >>= 1)
        s += __shfl_xor_sync(0xffffffffu, s, m);
    if (lane == 0) g_e2[row] = s;
}

// ---------------------------------------------------------------------------
// Fused: argmin GEMM (R2 mainloop) + y/idx/histogram/SSE epilogue.
// ---------------------------------------------------------------------------
__global__ void __launch_bounds__(256, 1)
vq_argmin_fused_kernel(const float* __restrict__ x, const float* __restrict__ cb,
                       float* __restrict__ y_out, float* __restrict__ idxf_out) {
    extern __shared__ float smem[];
    float*  xs    = smem;                          // 128*260
    float*  cs    = smem + 128 * 260;              // 2 * 32*CS_STRIDE
    float*  e2s   = cs + 2 * 32 * CS_STRIDE;       // 1024
    int*    idx_s = (int*)(e2s + 1024);            // 128
    double* wsum  = (double*)(idx_s + 128);        // 8

    const int tid = threadIdx.x;
    const int tx  = tid & 15;
    const int ty  = tid >> 4;
    const int n0  = blockIdx.x * BN;

    for (int i = tid; i < KCB; i += 256) e2s[i] = g_e2[i];

    const float4* __restrict__ x4 = (const float4*)x;
    float4* xs4 = (float4*)xs;
#pragma unroll
    for (int u = 0; u < 32; ++u) {
        int f  = tid + u * 256;
        int r  = f >> 6;
        int d4 = f & 63;
        float4 v = x4[(size_t)(n0 + r) * D4 + d4];
        xs4[r * XS_STRIDE4 + (d4 ^ ((r >> 3) & 7))] = v;
    }
    __syncthreads();

    // x2 per row (EXACT R2 chain)
    float x2r[8];
#pragma unroll
    for (int i = 0; i < 8; ++i) {
        int r  = ty * 8 + i;
        int sw = (r >> 3) & 7;
        float s = 0.0f;
#pragma unroll
        for (int q = 0; q < 4; ++q) {
            float4 v = xs4[r * XS_STRIDE4 + ((tx * 4 + q) ^ sw)];
            s = fmaf(v.x, v.x, s);
            s = fmaf(v.y, v.y, s);
            s = fmaf(v.z, v.z, s);
            s = fmaf(v.w, v.w, s);
        }
#pragma unroll
        for (int m = 8; m >= 1; m >>= 1)
            s += __shfl_xor_sync(0xffffffffu, s, m, 16);
        x2r[i] = s;
    }

    float rbd[8];
    int   rbk[8];
#pragma unroll
    for (int i = 0; i < 8; ++i) { rbd[i] = FLT_MAX; rbk[i] = 0; }

    const float4* __restrict__ cb4 = (const float4*)cb;

    // preload chunk 0 (kt=0, dt=0), transposed [dd][k]
    {
        float* dst = cs;
#pragma unroll
        for (int u = 0; u < 4; ++u) {
            int f   = tid + u * 256;
            int kl  = f >> 3;
            int dl4 = f & 7;
            float4 v = cb4[(size_t)kl * D4 + dl4];
            int ddb = dl4 * 4;
            dst[(ddb + 0) * CS_STRIDE + kl] = v.x;
            dst[(ddb + 1) * CS_STRIDE + kl] = v.y;
            dst[(ddb + 2) * CS_STRIDE + kl] = v.z;
            dst[(ddb + 3) * CS_STRIDE + kl] = v.w;
        }
    }
    __syncthreads();

    unsigned long long simp[8][4];

#pragma unroll 1
    for (int cc = 0; cc < 64; ++cc) {      // kt = cc>>3, dt = cc&7
        const int kt = cc >> 3;
        const int dt = cc & 7;

        if (dt == 0) {
#pragma unroll
            for (int i = 0; i < 8; ++i)
#pragma unroll
                for (int j = 0; j < 4; ++j) simp[i][j] = 0ull;
        }

        float4 pv[4];
        const bool have_next = (cc < 63);
        if (have_next) {
            int nkt = (cc + 1) >> 3, ndt = (cc + 1) & 7;
#pragma unroll
            for (int u = 0; u < 4; ++u) {
                int f   = tid + u * 256;
                int kl  = f >> 3;
                int dl4 = f & 7;
                pv[u] = cb4[(size_t)(nkt * 128 + kl) * D4 + ndt * 8 + dl4];
            }
        }

        const ulonglong2* csb2 =
            (const ulonglong2*)(cs + (cc & 1) * (32 * CS_STRIDE));
#pragma unroll
        for (int dd4 = 0; dd4 < 8; ++dd4) {
            float4 xv[8];
#pragma unroll
            for (int i = 0; i < 8; ++i) {
                int r = ty * 8 + i;
                xv[i] = xs4[r * XS_STRIDE4 + ((dt * 8 + dd4) ^ ((r >> 3) & 7))];
            }
#pragma unroll
            for (int t = 0; t < 4; ++t) {
                int dd = dd4 * 4 + t;
                ulonglong2 c01 = csb2[dd * 33 + tx * 2];
                ulonglong2 c23 = csb2[dd * 33 + tx * 2 + 1];
#pragma unroll
                for (int i = 0; i < 8; ++i) {
                    float xv_s = (t == 0) ? xv[i].x : (t == 1) ? xv[i].y
                               : (t == 2) ? xv[i].z : xv[i].w;
                    unsigned long long xp = bcast2(xv_s);
                    FMA2(simp[i][0], xp, c01.x);
                    FMA2(simp[i][1], xp, c01.y);
                    FMA2(simp[i][2], xp, c23.x);
                    FMA2(simp[i][3], xp, c23.y);
                }
            }
        }

        if (have_next) {
            float* dst = cs + ((cc + 1) & 1) * (32 * CS_STRIDE);
#pragma unroll
            for (int u = 0; u < 4; ++u) {
                int f   = tid + u * 256;
                int kl  = f >> 3;
                int ddb = (f & 7) * 4;
                dst[(ddb + 0) * CS_STRIDE + kl] = pv[u].x;
                dst[(ddb + 1) * CS_STRIDE + kl] = pv[u].y;
                dst[(ddb + 2) * CS_STRIDE + kl] = pv[u].z;
                dst[(ddb + 3) * CS_STRIDE + kl] = pv[u].w;
            }
        }

        // per-tile: local running best only (no shuffles; k ascending,
        // strict < keeps first -> identical selection to R2)
        if (dt == 7) {
            const int kb = kt * 128 + tx * 8;
            float4 ea = *(const float4*)&e2s[kb];
            float4 eb = *(const float4*)&e2s[kb + 4];
            float e2v[8] = { ea.x, ea.y, ea.z, ea.w, eb.x, eb.y, eb.z, eb.w };
#pragma unroll
            for (int i = 0; i < 8; ++i) {
#pragma unroll
                for (int jp = 0; jp < 4; ++jp) {
                    unsigned long long s = simp[i][jp];
                    float s0 = __uint_as_float((unsigned)s);
                    float s1 = __uint_as_float((unsigned)(s >> 32));
                    int k0 = kb + jp * 2;
                    float t1 = __fadd_rn(x2r[i], e2v[jp * 2]);
                    float d0 = __fadd_rn(t1, -__fmul_rn(2.0f, s0));
                    if (d0 < rbd[i]) { rbd[i] = d0; rbk[i] = k0; }
                    float t2 = __fadd_rn(x2r[i], e2v[jp * 2 + 1]);
                    float d1 = __fadd_rn(t2, -__fmul_rn(2.0f, s1));
                    if (d1 < rbd[i]) { rbd[i] = d1; rbk[i] = k0 + 1; }
                }
            }
        }
        __syncthreads();
    }

    // final cross-lane reduction (16-lane groups), write idx to smem
#pragma unroll
    for (int i = 0; i < 8; ++i) {
        float bd = rbd[i];
        int   bk = rbk[i];
#pragma unroll
        for (int m = 1; m < 16; m <<= 1) {
            float od = __shfl_xor_sync(0xffffffffu, bd, m, 16);
            int   ok = __shfl_xor_sync(0xffffffffu, bk, m, 16);
            if (od < bd || (od == bd && ok < bk)) { bd = od; bk = ok; }
        }
        if (tx == 0) idx_s[ty * 8 + i] = bk;
    }
    __syncthreads();

    // histogram + idx output
    if (tid < 128) {
        int k = idx_s[tid];
        atomicAdd(&g_counts[k], 1u);
        if (idxf_out) idxf_out[n0 + tid] = (float)k;
    }

    // fused gather: y = fl(x + fl(q - x)), x from smem (exact bits),
    // q from codebook (L2-hot); deterministic f64 SSE partial per CTA.
    float4* y4 = (float4*)y_out;
    double acc = 0.0;
#pragma unroll 4
    for (int u = 0; u < 32; ++u) {
        int f  = tid + u * 256;
        int r  = f >> 6;
        int d4 = f & 63;
        float4 xv = xs4[r * XS_STRIDE4 + (d4 ^ ((r >> 3) & 7))];
        int k = idx_s[r];
        float4 qv = __ldg(&cb4[(size_t)k * D4 + d4]);
        float tx_ = __fadd_rn(qv.x, -xv.x);
        float ty_ = __fadd_rn(qv.y, -xv.y);
        float tz_ = __fadd_rn(qv.z, -xv.z);
        float tw_ = __fadd_rn(qv.w, -xv.w);
        float4 yv;
        yv.x = __fadd_rn(xv.x, tx_);
        yv.y = __fadd_rn(xv.y, ty_);
        yv.z = __fadd_rn(xv.z, tz_);
        yv.w = __fadd_rn(xv.w, tw_);
        y4[(size_t)(n0 + r) * D4 + d4] = yv;
        acc += (double)tx_ * tx_ + (double)ty_ * ty_ +
               (double)tz_ * tz_ + (double)tw_ * tw_;
    }

    // deterministic reduction: warp shuffle then smem
#pragma unroll
    for (int m = 16; m >= 1; m >>= 1)
        acc += __shfl_xor_sync(0xffffffffu, acc, m);
    if ((tid & 31) == 0) wsum[tid >> 5] = acc;
    __syncthreads();
    if (tid == 0) {
        double s = 0.0;
#pragma unroll
        for (int i = 0; i < 8; ++i) s += wsum[i];
        g_partial[blockIdx.x] = s;
    }
}

__global__ void __launch_bounds__(1024)
vq_finalize_kernel(float* __restrict__ scal_out, int nblocks) {
    __shared__ double redH[1024];
    __shared__ double redU[1024];
    __shared__ double redS[1024];
    int t = threadIdx.x;

    double s = 0.0;
    for (int i = t; i < nblocks; i += 1024) s += g_partial[i];

    float p    = (float)g_counts[t] * (1.0f / 65536.0f);
    float term = p * log2f(p + 1e-10f);

    redH[t] = -(double)term;
    redU[t] = (p > 0.0f) ? 1.0 : 0.0;
    redS[t] = s;
    __syncthreads();
#pragma unroll
    for (int m = 512; m >= 1; m >>= 1) {
        if (t < m) {
            redH[t] += redH[t + m];
            redU[t] += redU[t + m];
            redS[t] += redS[t + m];
        }
        __syncthreads();
    }
    if (t == 0) {
        double mse  = redS[0] / (double)((size_t)N_FIXED * D);
        float  c     = (float)mse;
        float  loss  = __fadd_rn(__fmul_rn(0.25f, c), c);
        float  H     = (float)redH[0];
        float  perp  = expf(__fmul_rn(H, 0.69314718f));
        float  usage = (float)(redU[0] / 1024.0);
        scal_out[0] = loss;
        scal_out[1] = perp;
        scal_out[2] = usage;
        scal_out[3] = H;
    }
}

extern "C" void kernel_launch(void* const* d_in, const int* in_sizes, int n_in,
                              void* d_out, int out_size) {
    (void)n_in;
    const float* x  = (const float*)d_in[0];
    const float* cb = (const float*)d_in[1];
    float* out = (float*)d_out;

    const int    n  = in_sizes[0] / D;      // 65536
    const size_t ND = (size_t)n * D;

    const long long os = (long long)out_size;
    const int with_idx  = os >= (long long)(ND + (size_t)n);
    const int with_scal = os >= (long long)(ND + (size_t)n + 4);

    const size_t smem_bytes = (size_t)SMEM_FLOATS * sizeof(float);
    cudaFuncSetAttribute(vq_argmin_fused_kernel,
                         cudaFuncAttributeMaxDynamicSharedMemorySize,
                         (int)smem_bytes);

    vq_init_kernel<<<1, 1024>>>();
    vq_e2_kernel<<<KCB / 8, 256>>>(cb);
    vq_argmin_fused_kernel<<<n / BN, 256, smem_bytes>>>(
        x, cb, out, with_idx ? (out + ND) : (float*)0);
    if (with_scal)
        vq_finalize_kernel<<<1, 1024>>>(out + ND + n, n / BN);
}